// round 2
// baseline (speedup 1.0000x reference)
#include <cuda_runtime.h>
#include <cuda_bf16.h>
#include <math.h>

#define BATCH 8
#define SEQ   2048
#define EMBED 1024
#define HEAD  64
#define MROWS (BATCH * SEQ)          // 16384

// Scratch for projected q,k,v (device globals: no allocation allowed)
__device__ float g_q[MROWS * HEAD];
__device__ float g_k[MROWS * HEAD];
__device__ float g_v[MROWS * HEAD];

// ---------------------------------------------------------------------------
// Kernel 1: fused QKV projection.  out[mat] = x @ W[mat]
// x: [16384, 1024] row-major, W: [1024, 64] row-major.
// Tile: 128 rows x 64 cols, K-chunk 32. Block 256 threads, 8x4 microtile.
// grid = (16384/128, 3)
// ---------------------------------------------------------------------------
__global__ __launch_bounds__(256) void qkv_proj_kernel(
    const float* __restrict__ x,
    const float* __restrict__ Wq,
    const float* __restrict__ Wk,
    const float* __restrict__ Wv)
{
    const int mat = blockIdx.y;
    const float* __restrict__ W = (mat == 0) ? Wq : ((mat == 1) ? Wk : Wv);
    float* __restrict__ outp = (mat == 0) ? g_q : ((mat == 1) ? g_k : g_v);

    const int row0 = blockIdx.x * 128;
    const int tid = threadIdx.x;
    const int tx = tid & 15;   // column group: cols tx*4 .. tx*4+3
    const int ty = tid >> 4;   // row group:    rows ty*8 .. ty*8+7

    __shared__ float Xs[128][33];   // padded: row-stride 33 avoids conflicts
    __shared__ float Ws[32][64];

    float acc[8][4];
#pragma unroll
    for (int i = 0; i < 8; i++)
#pragma unroll
        for (int j = 0; j < 4; j++) acc[i][j] = 0.f;

    for (int k0 = 0; k0 < EMBED; k0 += 32) {
        // Load X tile: 128 rows x 32 cols = 1024 float4, 4 per thread
#pragma unroll
        for (int i = 0; i < 4; i++) {
            int idx = tid + i * 256;      // 0..1023
            int r   = idx >> 3;           // 8 float4 per row
            int c4  = idx & 7;
            float4 v = *(const float4*)&x[(size_t)(row0 + r) * EMBED + k0 + c4 * 4];
            Xs[r][c4 * 4 + 0] = v.x;
            Xs[r][c4 * 4 + 1] = v.y;
            Xs[r][c4 * 4 + 2] = v.z;
            Xs[r][c4 * 4 + 3] = v.w;
        }
        // Load W tile: 32 x 64 = 512 float4, 2 per thread
#pragma unroll
        for (int i = 0; i < 2; i++) {
            int idx = tid + i * 256;      // 0..511
            int r   = idx >> 4;           // 16 float4 per row
            int c4  = idx & 15;
            *(float4*)&Ws[r][c4 * 4] = *(const float4*)&W[(size_t)(k0 + r) * HEAD + c4 * 4];
        }
        __syncthreads();

#pragma unroll
        for (int kk = 0; kk < 32; kk++) {
            float4 bv = *(const float4*)&Ws[kk][tx * 4];
            float a[8];
#pragma unroll
            for (int i = 0; i < 8; i++) a[i] = Xs[ty * 8 + i][kk];
#pragma unroll
            for (int i = 0; i < 8; i++) {
                acc[i][0] += a[i] * bv.x;
                acc[i][1] += a[i] * bv.y;
                acc[i][2] += a[i] * bv.z;
                acc[i][3] += a[i] * bv.w;
            }
        }
        __syncthreads();
    }

#pragma unroll
    for (int i = 0; i < 8; i++) {
        float4 r4 = make_float4(acc[i][0], acc[i][1], acc[i][2], acc[i][3]);
        *(float4*)&outp[(size_t)(row0 + ty * 8 + i) * HEAD + tx * 4] = r4;
    }
}

// ---------------------------------------------------------------------------
// Kernel 2: causal flash attention, one thread per query row.
// Block = 128 threads = 128 query rows. K/V tiles of 64 keys in smem.
// Online softmax in 16-key chunks (keeps score array at 16 registers).
// grid = (SEQ/128, BATCH)
// ---------------------------------------------------------------------------
__global__ __launch_bounds__(128, 1) void attn_kernel(float* __restrict__ out)
{
    const int qb = blockIdx.x;
    const int b  = blockIdx.y;
    const int t  = qb * 128 + threadIdx.x;          // this thread's query index

    __shared__ float Ks[64][64];
    __shared__ float Vs[64][64];

    // Load q row into registers, fold in scale 1/sqrt(C) = 1/32
    float q[HEAD];
    {
        const float* qp = g_q + ((size_t)b * SEQ + t) * HEAD;
#pragma unroll
        for (int i = 0; i < 16; i++) {
            float4 v = *(const float4*)&qp[i * 4];
            q[i * 4 + 0] = v.x * 0.03125f;
            q[i * 4 + 1] = v.y * 0.03125f;
            q[i * 4 + 2] = v.z * 0.03125f;
            q[i * 4 + 3] = v.w * 0.03125f;
        }
    }

    float m = -INFINITY;
    float l = 0.f;
    float o[HEAD];
#pragma unroll
    for (int d = 0; d < HEAD; d++) o[d] = 0.f;

    const int ktiles = 2 * qb + 2;   // covers keys 0 .. qb*128+127

    for (int kt = 0; kt < ktiles; kt++) {
        const int kbase = kt * 64;
        // Cooperative tile load: 64 keys x 64 dims, contiguous in gmem
        {
            const float4* kp = (const float4*)(g_k + ((size_t)b * SEQ + kbase) * HEAD);
            const float4* vp = (const float4*)(g_v + ((size_t)b * SEQ + kbase) * HEAD);
            float4* ks4 = (float4*)Ks;
            float4* vs4 = (float4*)Vs;
#pragma unroll
            for (int i = 0; i < 8; i++) {
                int idx = threadIdx.x + i * 128;   // 0..1023 float4s
                ks4[idx] = kp[idx];
                vs4[idx] = vp[idx];
            }
        }
        __syncthreads();

        // Process the 64 keys in chunks of 16
#pragma unroll 1
        for (int c = 0; c < 64; c += 16) {
            if (kbase + c > t) continue;   // chunk fully in the masked region

            float s[16];
            // --- scores: 4 keys at a time over d ---
#pragma unroll
            for (int kk0 = 0; kk0 < 16; kk0 += 4) {
                float a0 = 0.f, a1 = 0.f, a2 = 0.f, a3 = 0.f;
#pragma unroll
                for (int d = 0; d < HEAD; d += 4) {
                    float4 k0 = *(const float4*)&Ks[c + kk0 + 0][d];
                    float4 k1 = *(const float4*)&Ks[c + kk0 + 1][d];
                    float4 k2 = *(const float4*)&Ks[c + kk0 + 2][d];
                    float4 k3 = *(const float4*)&Ks[c + kk0 + 3][d];
                    a0 += q[d] * k0.x; a0 += q[d + 1] * k0.y; a0 += q[d + 2] * k0.z; a0 += q[d + 3] * k0.w;
                    a1 += q[d] * k1.x; a1 += q[d + 1] * k1.y; a1 += q[d + 2] * k1.z; a1 += q[d + 3] * k1.w;
                    a2 += q[d] * k2.x; a2 += q[d + 1] * k2.y; a2 += q[d + 2] * k2.z; a2 += q[d + 3] * k2.w;
                    a3 += q[d] * k3.x; a3 += q[d + 1] * k3.y; a3 += q[d + 2] * k3.z; a3 += q[d + 3] * k3.w;
                }
                s[kk0 + 0] = a0; s[kk0 + 1] = a1; s[kk0 + 2] = a2; s[kk0 + 3] = a3;
            }

            // --- causal mask + running max ---
            float mt = m;
#pragma unroll
            for (int j = 0; j < 16; j++) {
                if (kbase + c + j > t) s[j] = -INFINITY;
                mt = fmaxf(mt, s[j]);
            }

            // --- rescale previous state ---
            float corr = __expf(m - mt);
            m = mt;
            l *= corr;
#pragma unroll
            for (int d = 0; d < HEAD; d++) o[d] *= corr;

            // --- exp + accumulate p @ V ---
#pragma unroll
            for (int j = 0; j < 16; j++) {
                float p = __expf(s[j] - mt);   // masked -> exp(-inf) = 0
                l += p;
#pragma unroll
                for (int d = 0; d < HEAD; d += 4) {
                    float4 vv = *(const float4*)&Vs[c + j][d];
                    o[d + 0] += p * vv.x;
                    o[d + 1] += p * vv.y;
                    o[d + 2] += p * vv.z;
                    o[d + 3] += p * vv.w;
                }
            }
        }
        __syncthreads();
    }

    // Normalize and store
    const float inv = 1.f / l;
    float* op = out + ((size_t)b * SEQ + t) * HEAD;
#pragma unroll
    for (int d = 0; d < HEAD; d += 4) {
        float4 r4 = make_float4(o[d] * inv, o[d + 1] * inv, o[d + 2] * inv, o[d + 3] * inv);
        *(float4*)&op[d] = r4;
    }
}

// ---------------------------------------------------------------------------
extern "C" void kernel_launch(void* const* d_in, const int* in_sizes, int n_in,
                              void* d_out, int out_size)
{
    const float* x  = (const float*)d_in[0];
    const float* Wq = (const float*)d_in[1];
    const float* Wk = (const float*)d_in[2];
    const float* Wv = (const float*)d_in[3];
    float* out = (float*)d_out;

    dim3 g1(MROWS / 128, 3);
    qkv_proj_kernel<<<g1, 256>>>(x, Wq, Wk, Wv);

    dim3 g2(SEQ / 128, BATCH);
    attn_kernel<<<g2, 128>>>(out);
}

// round 6
// speedup vs baseline: 3.5949x; 3.5949x over previous
#include <cuda_runtime.h>
#include <cuda_bf16.h>
#include <math.h>
#include <stdint.h>

#define BATCH 8
#define SEQ   2048
#define EMBED 1024
#define HEAD  64
#define MROWS (BATCH * SEQ)          // 16384

// Projected q,k,v as bf16 hi/lo pairs (q pre-scaled by 1/32).
__device__ __nv_bfloat16 g_qh[MROWS * HEAD];
__device__ __nv_bfloat16 g_ql[MROWS * HEAD];
__device__ __nv_bfloat16 g_kh[MROWS * HEAD];
__device__ __nv_bfloat16 g_kl[MROWS * HEAD];
__device__ __nv_bfloat16 g_vh[MROWS * HEAD];
__device__ __nv_bfloat16 g_vl[MROWS * HEAD];

// W transposed: row = mat*64 + n (0..191), col = k (0..1023), bf16 hi/lo.
__device__ __nv_bfloat16 g_wth[192 * 1024];
__device__ __nv_bfloat16 g_wtl[192 * 1024];

// ---------------------------------------------------------------------------
// Portable tensor-core helpers (mma.sync + ldmatrix, legal on compute_103)
// ---------------------------------------------------------------------------
__device__ __forceinline__ uint32_t smem_u32(const void* p) {
    uint32_t a;
    asm("{ .reg .u64 t; cvta.to.shared.u64 t, %1; cvt.u32.u64 %0, t; }" : "=r"(a) : "l"(p));
    return a;
}
__device__ __forceinline__ void ldsm4(uint32_t* r, uint32_t a) {
    asm volatile("ldmatrix.sync.aligned.m8n8.x4.shared.b16 {%0,%1,%2,%3}, [%4];"
        : "=r"(r[0]), "=r"(r[1]), "=r"(r[2]), "=r"(r[3]) : "r"(a));
}
__device__ __forceinline__ void ldsm2(uint32_t* r, uint32_t a) {
    asm volatile("ldmatrix.sync.aligned.m8n8.x2.shared.b16 {%0,%1}, [%2];"
        : "=r"(r[0]), "=r"(r[1]) : "r"(a));
}
__device__ __forceinline__ void ldsm2t(uint32_t* r, uint32_t a) {
    asm volatile("ldmatrix.sync.aligned.m8n8.x2.trans.shared.b16 {%0,%1}, [%2];"
        : "=r"(r[0]), "=r"(r[1]) : "r"(a));
}
// D += A(16x16) * B(16x8), bf16 in, fp32 accum
__device__ __forceinline__ void mma16816(float* c, const uint32_t* a, const uint32_t* b) {
    asm volatile("mma.sync.aligned.m16n8k16.row.col.f32.bf16.bf16.f32 "
        "{%0,%1,%2,%3}, {%4,%5,%6,%7}, {%8,%9}, {%0,%1,%2,%3};"
        : "+f"(c[0]), "+f"(c[1]), "+f"(c[2]), "+f"(c[3])
        : "r"(a[0]), "r"(a[1]), "r"(a[2]), "r"(a[3]), "r"(b[0]), "r"(b[1]));
}
// pack: low half = lo, high half = hi
__device__ __forceinline__ uint32_t f2bf2(float lo, float hi) {
    uint32_t r;
    asm("cvt.rn.bf16x2.f32 %0, %1, %2;" : "=r"(r) : "f"(hi), "f"(lo));
    return r;
}
__device__ __forceinline__ void split2(float v, float& hf, float& lf) {
    __nv_bfloat16 h = __float2bfloat16_rn(v);
    hf = __bfloat162float(h);
    lf = v - hf;
}
// hi/lo packed pair for two floats
__device__ __forceinline__ void splitpack(float v0, float v1, uint32_t& ph, uint32_t& pl) {
    float h0, l0, h1, l1;
    split2(v0, h0, l0); split2(v1, h1, l1);
    ph = f2bf2(h0, h1);
    pl = f2bf2(l0, l1);
}
__device__ __forceinline__ float qmax(float v) {
    v = fmaxf(v, __shfl_xor_sync(0xffffffffu, v, 1));
    v = fmaxf(v, __shfl_xor_sync(0xffffffffu, v, 2));
    return v;
}
__device__ __forceinline__ float qsum(float v) {
    v += __shfl_xor_sync(0xffffffffu, v, 1);
    v += __shfl_xor_sync(0xffffffffu, v, 2);
    return v;
}

#define PADB 144   // padded row pitch in bytes (72 bf16): conflict-free ldmatrix

// ---------------------------------------------------------------------------
// Kernel 0: W prep -> transposed bf16 hi/lo  (row = mat*64+n, col = k)
// ---------------------------------------------------------------------------
__global__ __launch_bounds__(256) void wprep_kernel(
    const float* __restrict__ Wq,
    const float* __restrict__ Wk,
    const float* __restrict__ Wv)
{
    int i = blockIdx.x * 256 + threadIdx.x;
    if (i >= 192 * 1024) return;
    int row = i >> 10;            // 0..191
    int k   = i & 1023;
    int mat = row >> 6;
    int n   = row & 63;
    const float* W = (mat == 0) ? Wq : ((mat == 1) ? Wk : Wv);
    float v = W[(size_t)k * HEAD + n];
    float hf, lf; split2(v, hf, lf);
    g_wth[i] = __float2bfloat16_rn(hf);
    g_wtl[i] = __float2bfloat16_rn(lf);
}

// ---------------------------------------------------------------------------
// Kernel 1: QKV projection.  D[128 x 192] = X[128 x 1024] @ [Wq|Wk|Wv]
// 8 warps: warp w -> rows (w>>1)*32, cols (w&1)*96 (2 mtiles x 12 ntiles).
// hi/lo bf16 3-term mma. Grid = 128, 256 threads.
// ---------------------------------------------------------------------------
#define PJ_XH  0
#define PJ_XL  18432
#define PJ_WH  36864
#define PJ_WL  64512
#define PJ_SMEM 92160

__global__ __launch_bounds__(256) void proj_kernel(const float* __restrict__ x)
{
    extern __shared__ char smem[];
    const uint32_t sb = smem_u32(smem);
    const int tid  = threadIdx.x;
    const int w    = tid >> 5;
    const int lane = tid & 31;
    const int r0   = (w >> 1) * 32;
    const int c0   = (w & 1) * 96;
    const int row0 = blockIdx.x * 128;

    float C[2][12][4];
#pragma unroll
    for (int mt = 0; mt < 2; mt++)
#pragma unroll
        for (int nt = 0; nt < 12; nt++)
#pragma unroll
            for (int e = 0; e < 4; e++) C[mt][nt][e] = 0.f;

    // ldmatrix lane addressing pieces
    const int a_row = (lane & 7) + ((lane >> 3) & 1) * 8;   // row within 16
    const int a_c16 = ((lane >> 4) & 1) * 16;               // byte col within 32
    const int b_row = lane & 7;
    const int b_c16 = ((lane >> 3) & 1) * 16;

    for (int c = 0; c < 16; c++) {
        const int k0 = c * 64;
        // X chunk: 128 rows x 64 k fp32 -> hi/lo bf16 smem
        for (int i = tid; i < 2048; i += 256) {
            int r = i >> 4, c4 = i & 15;
            float4 v = *(const float4*)&x[(size_t)(row0 + r) * EMBED + k0 + c4 * 4];
            float h0, l0, h1, l1, h2, l2, h3, l3;
            split2(v.x, h0, l0); split2(v.y, h1, l1);
            split2(v.z, h2, l2); split2(v.w, h3, l3);
            int off = r * PADB + c4 * 8;
            *(uint32_t*)(smem + PJ_XH + off)     = f2bf2(h0, h1);
            *(uint32_t*)(smem + PJ_XH + off + 4) = f2bf2(h2, h3);
            *(uint32_t*)(smem + PJ_XL + off)     = f2bf2(l0, l1);
            *(uint32_t*)(smem + PJ_XL + off + 4) = f2bf2(l2, l3);
        }
        // W chunk: 192 rows x 64 k bf16 (straight copy, uint4)
        for (int i = tid; i < 1536; i += 256) {
            int row = i >> 3, d8 = i & 7;
            size_t src = ((size_t)row * 1024 + k0) / 8 + d8;
            int off = row * PADB + d8 * 16;
            *(uint4*)(smem + PJ_WH + off) = ((const uint4*)g_wth)[src];
            *(uint4*)(smem + PJ_WL + off) = ((const uint4*)g_wtl)[src];
        }
        __syncthreads();

#pragma unroll
        for (int kt = 0; kt < 4; kt++) {
            uint32_t Ah[2][4], Al[2][4];
#pragma unroll
            for (int mt = 0; mt < 2; mt++) {
                uint32_t ao = (uint32_t)((r0 + mt * 16 + a_row) * PADB + kt * 32 + a_c16);
                ldsm4(Ah[mt], sb + PJ_XH + ao);
                ldsm4(Al[mt], sb + PJ_XL + ao);
            }
#pragma unroll
            for (int nt = 0; nt < 12; nt++) {
                uint32_t bo = (uint32_t)((c0 + nt * 8 + b_row) * PADB + kt * 32 + b_c16);
                uint32_t Bh[2], Bl[2];
                ldsm2(Bh, sb + PJ_WH + bo);
                ldsm2(Bl, sb + PJ_WL + bo);
#pragma unroll
                for (int mt = 0; mt < 2; mt++) {
                    mma16816(C[mt][nt], Ah[mt], Bh);
                    mma16816(C[mt][nt], Ah[mt], Bl);
                    mma16816(C[mt][nt], Al[mt], Bh);
                }
            }
        }
        __syncthreads();
    }

    // Epilogue: write q (x1/32), k, v as bf16 hi/lo
#pragma unroll
    for (int mt = 0; mt < 2; mt++) {
#pragma unroll
        for (int nt = 0; nt < 12; nt++) {
            int col = c0 + nt * 8 + (lane & 3) * 2;
            int mat = col >> 6;
            int cc  = col & 63;
            __nv_bfloat16* gh = (mat == 0) ? g_qh : ((mat == 1) ? g_kh : g_vh);
            __nv_bfloat16* gl = (mat == 0) ? g_ql : ((mat == 1) ? g_kl : g_vl);
            float s = (mat == 0) ? 0.03125f : 1.0f;
            int row_a = row0 + r0 + mt * 16 + (lane >> 2);
#pragma unroll
            for (int h = 0; h < 2; h++) {
                int row = row_a + h * 8;
                float v0 = C[mt][nt][2 * h] * s, v1 = C[mt][nt][2 * h + 1] * s;
                uint32_t ph, pl; splitpack(v0, v1, ph, pl);
                *(uint32_t*)&gh[(size_t)row * HEAD + cc] = ph;
                *(uint32_t*)&gl[(size_t)row * HEAD + cc] = pl;
            }
        }
    }
}

// ---------------------------------------------------------------------------
// Kernel 2: causal flash attention (FA2 style, mma.sync).
// CTA: 128 threads (4 warps), 128 q rows; warp w -> rows w*32 (2 mtiles).
// Key tiles of 64. Grid = (16, 8).
// ---------------------------------------------------------------------------
#define AT_QH  0
#define AT_QL  18432
#define AT_KH  36864
#define AT_KL  46080
#define AT_VH  55296
#define AT_VL  64512
#define AT_SMEM 73728

__global__ __launch_bounds__(128) void attn_kernel(float* __restrict__ out)
{
    extern __shared__ char smem[];
    const uint32_t sb = smem_u32(smem);
    const int tid  = threadIdx.x;
    const int w    = tid >> 5;
    const int lane = tid & 31;
    const int qb   = blockIdx.x;
    const int b    = blockIdx.y;
    const int qbase = qb * 128;

    // Load Q tile hi/lo into padded smem
    {
        const uint4* qh = (const uint4*)(g_qh + ((size_t)b * SEQ + qbase) * HEAD);
        const uint4* ql = (const uint4*)(g_ql + ((size_t)b * SEQ + qbase) * HEAD);
        for (int i = tid; i < 2048; i += 128) {
            int arr = i >> 10, rem = i & 1023;
            int r = rem >> 3, d8 = rem & 7;
            int off = (arr ? AT_QL : AT_QH) + r * PADB + d8 * 16;
            *(uint4*)(smem + off) = (arr ? ql : qh)[rem];
        }
    }

    float O[2][8][4];
    float m_[2][2], l_[2][2];
#pragma unroll
    for (int mt = 0; mt < 2; mt++) {
#pragma unroll
        for (int nd = 0; nd < 8; nd++)
#pragma unroll
            for (int e = 0; e < 4; e++) O[mt][nd][e] = 0.f;
        m_[mt][0] = m_[mt][1] = -1e30f;
        l_[mt][0] = l_[mt][1] = 0.f;
    }

    const int a_row = (lane & 7) + ((lane >> 3) & 1) * 8;
    const int a_c16 = ((lane >> 4) & 1) * 16;
    const int b_row = lane & 7;
    const int b_c16 = ((lane >> 3) & 1) * 16;
    const int v_row = lane & 15;

    const int nkt = 2 * qb + 2;
    for (int kt_i = 0; kt_i < nkt; kt_i++) {
        const int kbase = kt_i * 64;
        // Load K/V tiles hi/lo
        {
            const uint4* kh = (const uint4*)(g_kh + ((size_t)b * SEQ + kbase) * HEAD);
            const uint4* kl = (const uint4*)(g_kl + ((size_t)b * SEQ + kbase) * HEAD);
            const uint4* vh = (const uint4*)(g_vh + ((size_t)b * SEQ + kbase) * HEAD);
            const uint4* vl = (const uint4*)(g_vl + ((size_t)b * SEQ + kbase) * HEAD);
            for (int i = tid; i < 2048; i += 128) {
                int arr = i >> 9, rem = i & 511;
                int r = rem >> 3, d8 = rem & 7;
                const uint4* src = (arr == 0) ? kh : ((arr == 1) ? kl : ((arr == 2) ? vh : vl));
                int base = (arr == 0) ? AT_KH : ((arr == 1) ? AT_KL : ((arr == 2) ? AT_VH : AT_VL));
                *(uint4*)(smem + base + r * PADB + d8 * 16) = src[rem];
            }
        }
        __syncthreads();

        // ---- S = Q @ K^T ----
        float S[2][8][4];
#pragma unroll
        for (int mt = 0; mt < 2; mt++)
#pragma unroll
            for (int nt = 0; nt < 8; nt++)
#pragma unroll
                for (int e = 0; e < 4; e++) S[mt][nt][e] = 0.f;

#pragma unroll
        for (int kt = 0; kt < 4; kt++) {
            uint32_t Ah[2][4], Al[2][4];
#pragma unroll
            for (int mt = 0; mt < 2; mt++) {
                uint32_t ao = (uint32_t)((w * 32 + mt * 16 + a_row) * PADB + kt * 32 + a_c16);
                ldsm4(Ah[mt], sb + AT_QH + ao);
                ldsm4(Al[mt], sb + AT_QL + ao);
            }
#pragma unroll
            for (int nt = 0; nt < 8; nt++) {
                uint32_t bo = (uint32_t)((nt * 8 + b_row) * PADB + kt * 32 + b_c16);
                uint32_t Bh[2], Bl[2];
                ldsm2(Bh, sb + AT_KH + bo);
                ldsm2(Bl, sb + AT_KL + bo);
#pragma unroll
                for (int mt = 0; mt < 2; mt++) {
                    mma16816(S[mt][nt], Ah[mt], Bh);
                    mma16816(S[mt][nt], Ah[mt], Bl);
                    mma16816(S[mt][nt], Al[mt], Bh);
                }
            }
        }

        // ---- mask + online softmax ----
        const bool need_mask = (kbase + 64 > qbase);
#pragma unroll
        for (int mt = 0; mt < 2; mt++) {
            if (need_mask) {
                int rbase = qbase + w * 32 + mt * 16 + (lane >> 2);
#pragma unroll
                for (int nt = 0; nt < 8; nt++) {
                    int cb = kbase + nt * 8 + (lane & 3) * 2;
#pragma unroll
                    for (int e = 0; e < 4; e++) {
                        int row = rbase + (e >> 1) * 8;
                        int col = cb + (e & 1);
                        if (col > row) S[mt][nt][e] = -1e30f;
                    }
                }
            }
#pragma unroll
            for (int h = 0; h < 2; h++) {
                float rm = -1e30f;
#pragma unroll
                for (int nt = 0; nt < 8; nt++)
                    rm = fmaxf(rm, fmaxf(S[mt][nt][2 * h], S[mt][nt][2 * h + 1]));
                rm = qmax(rm);
                float mn = fmaxf(m_[mt][h], rm);
                float sc = __expf(m_[mt][h] - mn);
                m_[mt][h] = mn;
                float rs = 0.f;
#pragma unroll
                for (int nt = 0; nt < 8; nt++) {
                    float p0 = __expf(S[mt][nt][2 * h] - mn);
                    float p1 = __expf(S[mt][nt][2 * h + 1] - mn);
                    S[mt][nt][2 * h] = p0; S[mt][nt][2 * h + 1] = p1;
                    rs += p0 + p1;
                }
                rs = qsum(rs);
                l_[mt][h] = l_[mt][h] * sc + rs;
#pragma unroll
                for (int nd = 0; nd < 8; nd++) {
                    O[mt][nd][2 * h]     *= sc;
                    O[mt][nd][2 * h + 1] *= sc;
                }
            }
        }

        // ---- O += P @ V ----
#pragma unroll
        for (int kt = 0; kt < 4; kt++) {
            uint32_t Ph[2][4], Pl[2][4];
#pragma unroll
            for (int mt = 0; mt < 2; mt++) {
                splitpack(S[mt][2 * kt][0],     S[mt][2 * kt][1],     Ph[mt][0], Pl[mt][0]);
                splitpack(S[mt][2 * kt][2],     S[mt][2 * kt][3],     Ph[mt][1], Pl[mt][1]);
                splitpack(S[mt][2 * kt + 1][0], S[mt][2 * kt + 1][1], Ph[mt][2], Pl[mt][2]);
                splitpack(S[mt][2 * kt + 1][2], S[mt][2 * kt + 1][3], Ph[mt][3], Pl[mt][3]);
            }
#pragma unroll
            for (int nd = 0; nd < 8; nd++) {
                uint32_t vo = (uint32_t)((kt * 16 + v_row) * PADB + nd * 16);
                uint32_t Bh[2], Bl[2];
                ldsm2t(Bh, sb + AT_VH + vo);
                ldsm2t(Bl, sb + AT_VL + vo);
#pragma unroll
                for (int mt = 0; mt < 2; mt++) {
                    mma16816(O[mt][nd], Ph[mt], Bh);
                    mma16816(O[mt][nd], Ph[mt], Bl);
                    mma16816(O[mt][nd], Pl[mt], Bh);
                }
            }
        }
        __syncthreads();
    }

    // ---- store ----
#pragma unroll
    for (int mt = 0; mt < 2; mt++) {
        float inv0 = 1.f / l_[mt][0];
        float inv1 = 1.f / l_[mt][1];
        int row_a = qbase + w * 32 + mt * 16 + (lane >> 2);
#pragma unroll
        for (int nd = 0; nd < 8; nd++) {
            int col = nd * 8 + (lane & 3) * 2;
            float2 v0 = make_float2(O[mt][nd][0] * inv0, O[mt][nd][1] * inv0);
            float2 v1 = make_float2(O[mt][nd][2] * inv1, O[mt][nd][3] * inv1);
            *(float2*)&out[((size_t)b * SEQ + row_a) * HEAD + col]     = v0;
            *(float2*)&out[((size_t)b * SEQ + row_a + 8) * HEAD + col] = v1;
        }
    }
}

// ---------------------------------------------------------------------------
extern "C" void kernel_launch(void* const* d_in, const int* in_sizes, int n_in,
                              void* d_out, int out_size)
{
    const float* x  = (const float*)d_in[0];
    const float* Wq = (const float*)d_in[1];
    const float* Wk = (const float*)d_in[2];
    const float* Wv = (const float*)d_in[3];
    float* out = (float*)d_out;

    cudaFuncSetAttribute(proj_kernel, cudaFuncAttributeMaxDynamicSharedMemorySize, PJ_SMEM);
    cudaFuncSetAttribute(attn_kernel, cudaFuncAttributeMaxDynamicSharedMemorySize, AT_SMEM);

    wprep_kernel<<<(192 * 1024 + 255) / 256, 256>>>(Wq, Wk, Wv);
    proj_kernel<<<128, 256, PJ_SMEM>>>(x);

    dim3 g2(SEQ / 128, BATCH);
    attn_kernel<<<g2, 128, AT_SMEM>>>(out);
}

// round 7
// speedup vs baseline: 6.1738x; 1.7174x over previous
#include <cuda_runtime.h>
#include <cuda_bf16.h>
#include <math.h>
#include <stdint.h>

#define BATCH 8
#define SEQ   2048
#define EMBED 1024
#define HEAD  64
#define MROWS (BATCH * SEQ)          // 16384

// Projected q,k,v as bf16 hi/lo pairs (q pre-scaled by 1/32).
__device__ __nv_bfloat16 g_qh[MROWS * HEAD];
__device__ __nv_bfloat16 g_ql[MROWS * HEAD];
__device__ __nv_bfloat16 g_kh[MROWS * HEAD];
__device__ __nv_bfloat16 g_kl[MROWS * HEAD];
__device__ __nv_bfloat16 g_vh[MROWS * HEAD];
__device__ __nv_bfloat16 g_vl[MROWS * HEAD];

// W transposed: row = mat*64 + n (0..191), col = k (0..1023), bf16 hi/lo.
__device__ __nv_bfloat16 g_wth[192 * 1024];
__device__ __nv_bfloat16 g_wtl[192 * 1024];

// ---------------------------------------------------------------------------
// Portable tensor-core helpers (mma.sync + ldmatrix + cp.async; compute_103-legal)
// ---------------------------------------------------------------------------
__device__ __forceinline__ uint32_t smem_u32(const void* p) {
    uint32_t a;
    asm("{ .reg .u64 t; cvta.to.shared.u64 t, %1; cvt.u32.u64 %0, t; }" : "=r"(a) : "l"(p));
    return a;
}
__device__ __forceinline__ void ldsm4(uint32_t* r, uint32_t a) {
    asm volatile("ldmatrix.sync.aligned.m8n8.x4.shared.b16 {%0,%1,%2,%3}, [%4];"
        : "=r"(r[0]), "=r"(r[1]), "=r"(r[2]), "=r"(r[3]) : "r"(a));
}
__device__ __forceinline__ void ldsm2(uint32_t* r, uint32_t a) {
    asm volatile("ldmatrix.sync.aligned.m8n8.x2.shared.b16 {%0,%1}, [%2];"
        : "=r"(r[0]), "=r"(r[1]) : "r"(a));
}
__device__ __forceinline__ void ldsm2t(uint32_t* r, uint32_t a) {
    asm volatile("ldmatrix.sync.aligned.m8n8.x2.trans.shared.b16 {%0,%1}, [%2];"
        : "=r"(r[0]), "=r"(r[1]) : "r"(a));
}
__device__ __forceinline__ void mma16816(float* c, const uint32_t* a, const uint32_t* b) {
    asm volatile("mma.sync.aligned.m16n8k16.row.col.f32.bf16.bf16.f32 "
        "{%0,%1,%2,%3}, {%4,%5,%6,%7}, {%8,%9}, {%0,%1,%2,%3};"
        : "+f"(c[0]), "+f"(c[1]), "+f"(c[2]), "+f"(c[3])
        : "r"(a[0]), "r"(a[1]), "r"(a[2]), "r"(a[3]), "r"(b[0]), "r"(b[1]));
}
__device__ __forceinline__ uint32_t f2bf2(float lo, float hi) {
    uint32_t r;
    asm("cvt.rn.bf16x2.f32 %0, %1, %2;" : "=r"(r) : "f"(hi), "f"(lo));
    return r;
}
__device__ __forceinline__ void split2(float v, float& hf, float& lf) {
    __nv_bfloat16 h = __float2bfloat16_rn(v);
    hf = __bfloat162float(h);
    lf = v - hf;
}
__device__ __forceinline__ void splitpack(float v0, float v1, uint32_t& ph, uint32_t& pl) {
    float h0, l0, h1, l1;
    split2(v0, h0, l0); split2(v1, h1, l1);
    ph = f2bf2(h0, h1);
    pl = f2bf2(l0, l1);
}
__device__ __forceinline__ float qmax(float v) {
    v = fmaxf(v, __shfl_xor_sync(0xffffffffu, v, 1));
    v = fmaxf(v, __shfl_xor_sync(0xffffffffu, v, 2));
    return v;
}
__device__ __forceinline__ float qsum(float v) {
    v += __shfl_xor_sync(0xffffffffu, v, 1);
    v += __shfl_xor_sync(0xffffffffu, v, 2);
    return v;
}
__device__ __forceinline__ void cp16(uint32_t dst, const void* src) {
    asm volatile("cp.async.cg.shared.global [%0], [%1], 16;" :: "r"(dst), "l"(src));
}
#define CP_COMMIT() asm volatile("cp.async.commit_group;" ::: "memory")
#define CP_WAIT(n)  asm volatile("cp.async.wait_group %0;" :: "n"(n) : "memory")

#define PADB 144   // padded row pitch in bytes (72 bf16): conflict-free ldmatrix

// ---------------------------------------------------------------------------
// Kernel 0: W prep -> transposed bf16 hi/lo  (row = mat*64+n, col = k)
// ---------------------------------------------------------------------------
__global__ __launch_bounds__(256) void wprep_kernel(
    const float* __restrict__ Wq,
    const float* __restrict__ Wk,
    const float* __restrict__ Wv)
{
    int i = blockIdx.x * 256 + threadIdx.x;
    if (i >= 192 * 1024) return;
    int row = i >> 10;
    int k   = i & 1023;
    int mat = row >> 6;
    int n   = row & 63;
    const float* W = (mat == 0) ? Wq : ((mat == 1) ? Wk : Wv);
    float v = W[(size_t)k * HEAD + n];
    float hf, lf; split2(v, hf, lf);
    g_wth[i] = __float2bfloat16_rn(hf);
    g_wtl[i] = __float2bfloat16_rn(lf);
}

// ---------------------------------------------------------------------------
// Kernel 1: QKV projection.  D[128 x 192] = X[128 x 1024] @ [Wq|Wk|Wv]
// (unchanged from R6 — passed)
// ---------------------------------------------------------------------------
#define PJ_XH  0
#define PJ_XL  18432
#define PJ_WH  36864
#define PJ_WL  64512
#define PJ_SMEM 92160

__global__ __launch_bounds__(256) void proj_kernel(const float* __restrict__ x)
{
    extern __shared__ char smem[];
    const uint32_t sb = smem_u32(smem);
    const int tid  = threadIdx.x;
    const int w    = tid >> 5;
    const int lane = tid & 31;
    const int r0   = (w >> 1) * 32;
    const int c0   = (w & 1) * 96;
    const int row0 = blockIdx.x * 128;

    float C[2][12][4];
#pragma unroll
    for (int mt = 0; mt < 2; mt++)
#pragma unroll
        for (int nt = 0; nt < 12; nt++)
#pragma unroll
            for (int e = 0; e < 4; e++) C[mt][nt][e] = 0.f;

    const int a_row = (lane & 7) + ((lane >> 3) & 1) * 8;
    const int a_c16 = ((lane >> 4) & 1) * 16;
    const int b_row = lane & 7;
    const int b_c16 = ((lane >> 3) & 1) * 16;

    for (int c = 0; c < 16; c++) {
        const int k0 = c * 64;
        for (int i = tid; i < 2048; i += 256) {
            int r = i >> 4, c4 = i & 15;
            float4 v = *(const float4*)&x[(size_t)(row0 + r) * EMBED + k0 + c4 * 4];
            float h0, l0, h1, l1, h2, l2, h3, l3;
            split2(v.x, h0, l0); split2(v.y, h1, l1);
            split2(v.z, h2, l2); split2(v.w, h3, l3);
            int off = r * PADB + c4 * 8;
            *(uint32_t*)(smem + PJ_XH + off)     = f2bf2(h0, h1);
            *(uint32_t*)(smem + PJ_XH + off + 4) = f2bf2(h2, h3);
            *(uint32_t*)(smem + PJ_XL + off)     = f2bf2(l0, l1);
            *(uint32_t*)(smem + PJ_XL + off + 4) = f2bf2(l2, l3);
        }
        for (int i = tid; i < 1536; i += 256) {
            int row = i >> 3, d8 = i & 7;
            size_t src = ((size_t)row * 1024 + k0) / 8 + d8;
            int off = row * PADB + d8 * 16;
            *(uint4*)(smem + PJ_WH + off) = ((const uint4*)g_wth)[src];
            *(uint4*)(smem + PJ_WL + off) = ((const uint4*)g_wtl)[src];
        }
        __syncthreads();

#pragma unroll
        for (int kt = 0; kt < 4; kt++) {
            uint32_t Ah[2][4], Al[2][4];
#pragma unroll
            for (int mt = 0; mt < 2; mt++) {
                uint32_t ao = (uint32_t)((r0 + mt * 16 + a_row) * PADB + kt * 32 + a_c16);
                ldsm4(Ah[mt], sb + PJ_XH + ao);
                ldsm4(Al[mt], sb + PJ_XL + ao);
            }
#pragma unroll
            for (int nt = 0; nt < 12; nt++) {
                uint32_t bo = (uint32_t)((c0 + nt * 8 + b_row) * PADB + kt * 32 + b_c16);
                uint32_t Bh[2], Bl[2];
                ldsm2(Bh, sb + PJ_WH + bo);
                ldsm2(Bl, sb + PJ_WL + bo);
#pragma unroll
                for (int mt = 0; mt < 2; mt++) {
                    mma16816(C[mt][nt], Ah[mt], Bh);
                    mma16816(C[mt][nt], Ah[mt], Bl);
                    mma16816(C[mt][nt], Al[mt], Bh);
                }
            }
        }
        __syncthreads();
    }

#pragma unroll
    for (int mt = 0; mt < 2; mt++) {
#pragma unroll
        for (int nt = 0; nt < 12; nt++) {
            int col = c0 + nt * 8 + (lane & 3) * 2;
            int mat = col >> 6;
            int cc  = col & 63;
            __nv_bfloat16* gh = (mat == 0) ? g_qh : ((mat == 1) ? g_kh : g_vh);
            __nv_bfloat16* gl = (mat == 0) ? g_ql : ((mat == 1) ? g_kl : g_vl);
            float s = (mat == 0) ? 0.03125f : 1.0f;
            int row_a = row0 + r0 + mt * 16 + (lane >> 2);
#pragma unroll
            for (int h = 0; h < 2; h++) {
                int row = row_a + h * 8;
                float v0 = C[mt][nt][2 * h] * s, v1 = C[mt][nt][2 * h + 1] * s;
                uint32_t ph, pl; splitpack(v0, v1, ph, pl);
                *(uint32_t*)&gh[(size_t)row * HEAD + cc] = ph;
                *(uint32_t*)&gl[(size_t)row * HEAD + cc] = pl;
            }
        }
    }
}

// ---------------------------------------------------------------------------
// Kernel 2: causal flash attention, balanced + pipelined.
// CTA = 128 threads (4 warps), 64 q rows (warp w -> rows w*16..w*16+15).
// Grid (32, 8); qb = 31 - blockIdx.x (heavy CTAs first). ntiles = qb+1 key
// tiles of 64. cp.async double-buffered K/V; 2 CTAs/SM.
// ---------------------------------------------------------------------------
#define AT_QH   0
#define AT_QL   9216
#define AT_BUF0 18432
#define AT_BUF1 55296
#define AT_KHO  0
#define AT_KLO  9216
#define AT_VHO  18432
#define AT_VLO  27648
#define AT_SMEM 92160

__global__ __launch_bounds__(128) void attn_kernel(float* __restrict__ out)
{
    extern __shared__ char smem[];
    const uint32_t sb = smem_u32(smem);
    const int tid  = threadIdx.x;
    const int w    = tid >> 5;
    const int lane = tid & 31;
    const int qb   = 31 - blockIdx.x;      // heavy first
    const int b    = blockIdx.y;
    const int qbase = qb * 64;
    const int ntiles = qb + 1;

    // Q tile (64 x 64, hi/lo) — plain loads, once
    {
        const uint4* qh = (const uint4*)(g_qh + ((size_t)b * SEQ + qbase) * HEAD);
        const uint4* ql = (const uint4*)(g_ql + ((size_t)b * SEQ + qbase) * HEAD);
        for (int i = tid; i < 1024; i += 128) {
            int arr = i >> 9, rem = i & 511;
            int r = rem >> 3, d8 = rem & 7;
            int off = (arr ? AT_QL : AT_QH) + r * PADB + d8 * 16;
            *(uint4*)(smem + off) = (arr ? ql : qh)[rem];
        }
    }

    // cp.async tile issue: 4 arrays x 512 lines of 16B
    auto issue_tile = [&](int kt, int buf) {
        const int kbase = kt * 64;
        const size_t gb = ((size_t)b * SEQ + kbase) * HEAD;
        const uint32_t bufb = sb + (buf ? AT_BUF1 : AT_BUF0);
#pragma unroll
        for (int i = tid; i < 2048; i += 128) {
            int arr = i >> 9, rem = i & 511;
            int r = rem >> 3, d8 = rem & 7;
            const __nv_bfloat16* src =
                (arr == 0) ? g_kh : ((arr == 1) ? g_kl : ((arr == 2) ? g_vh : g_vl));
            int aoff = (arr == 0) ? AT_KHO : ((arr == 1) ? AT_KLO : ((arr == 2) ? AT_VHO : AT_VLO));
            cp16(bufb + aoff + r * PADB + d8 * 16, src + gb + (size_t)r * HEAD + d8 * 8);
        }
        CP_COMMIT();
    };

    float O[8][4];
    float m_[2], l_[2];
#pragma unroll
    for (int nd = 0; nd < 8; nd++)
#pragma unroll
        for (int e = 0; e < 4; e++) O[nd][e] = 0.f;
    m_[0] = m_[1] = -1e30f;
    l_[0] = l_[1] = 0.f;

    const int a_row = (lane & 7) + ((lane >> 3) & 1) * 8;
    const int a_c16 = ((lane >> 4) & 1) * 16;
    const int b_row = lane & 7;
    const int b_c16 = ((lane >> 3) & 1) * 16;
    const int v_row = lane & 15;

    issue_tile(0, 0);

    for (int kt = 0; kt < ntiles; kt++) {
        const int cur = kt & 1;
        if (kt + 1 < ntiles) { issue_tile(kt + 1, 1 - cur); CP_WAIT(1); }
        else                 { CP_WAIT(0); }
        __syncthreads();

        const uint32_t bufb = sb + (cur ? AT_BUF1 : AT_BUF0);
        const int kbase = kt * 64;

        // ---- S = Q @ K^T ----
        float S[8][4];
#pragma unroll
        for (int nt = 0; nt < 8; nt++)
#pragma unroll
            for (int e = 0; e < 4; e++) S[nt][e] = 0.f;

#pragma unroll
        for (int k4 = 0; k4 < 4; k4++) {
            uint32_t Ah[4], Al[4];
            uint32_t ao = (uint32_t)((w * 16 + a_row) * PADB + k4 * 32 + a_c16);
            ldsm4(Ah, sb + AT_QH + ao);
            ldsm4(Al, sb + AT_QL + ao);
#pragma unroll
            for (int nt = 0; nt < 8; nt++) {
                uint32_t bo = (uint32_t)((nt * 8 + b_row) * PADB + k4 * 32 + b_c16);
                uint32_t Bh[2], Bl[2];
                ldsm2(Bh, bufb + AT_KHO + bo);
                ldsm2(Bl, bufb + AT_KLO + bo);
                mma16816(S[nt], Ah, Bh);
                mma16816(S[nt], Ah, Bl);
                mma16816(S[nt], Al, Bh);
            }
        }

        // ---- mask (diagonal tile only) + online softmax ----
        if (kt == ntiles - 1) {
            int rbase = qbase + w * 16 + (lane >> 2);
#pragma unroll
            for (int nt = 0; nt < 8; nt++) {
                int cb = kbase + nt * 8 + (lane & 3) * 2;
#pragma unroll
                for (int e = 0; e < 4; e++) {
                    int row = rbase + (e >> 1) * 8;
                    int col = cb + (e & 1);
                    if (col > row) S[nt][e] = -1e30f;
                }
            }
        }
#pragma unroll
        for (int h = 0; h < 2; h++) {
            float rm = -1e30f;
#pragma unroll
            for (int nt = 0; nt < 8; nt++)
                rm = fmaxf(rm, fmaxf(S[nt][2 * h], S[nt][2 * h + 1]));
            rm = qmax(rm);
            float mn = fmaxf(m_[h], rm);
            float sc = __expf(m_[h] - mn);
            m_[h] = mn;
            float rs = 0.f;
#pragma unroll
            for (int nt = 0; nt < 8; nt++) {
                float p0 = __expf(S[nt][2 * h] - mn);
                float p1 = __expf(S[nt][2 * h + 1] - mn);
                S[nt][2 * h] = p0; S[nt][2 * h + 1] = p1;
                rs += p0 + p1;
            }
            rs = qsum(rs);
            l_[h] = l_[h] * sc + rs;
#pragma unroll
            for (int nd = 0; nd < 8; nd++) {
                O[nd][2 * h]     *= sc;
                O[nd][2 * h + 1] *= sc;
            }
        }

        // ---- O += P @ V ----
#pragma unroll
        for (int k4 = 0; k4 < 4; k4++) {
            uint32_t Ph[4], Pl[4];
            splitpack(S[2 * k4][0],     S[2 * k4][1],     Ph[0], Pl[0]);
            splitpack(S[2 * k4][2],     S[2 * k4][3],     Ph[1], Pl[1]);
            splitpack(S[2 * k4 + 1][0], S[2 * k4 + 1][1], Ph[2], Pl[2]);
            splitpack(S[2 * k4 + 1][2], S[2 * k4 + 1][3], Ph[3], Pl[3]);
#pragma unroll
            for (int nd = 0; nd < 8; nd++) {
                uint32_t vo = (uint32_t)((k4 * 16 + v_row) * PADB + nd * 16);
                uint32_t Bh[2], Bl[2];
                ldsm2t(Bh, bufb + AT_VHO + vo);
                ldsm2t(Bl, bufb + AT_VLO + vo);
                mma16816(O[nd], Ph, Bh);
                mma16816(O[nd], Ph, Bl);
                mma16816(O[nd], Pl, Bh);
            }
        }
        __syncthreads();
    }

    // ---- store ----
    float inv0 = 1.f / l_[0];
    float inv1 = 1.f / l_[1];
    int row_a = qbase + w * 16 + (lane >> 2);
#pragma unroll
    for (int nd = 0; nd < 8; nd++) {
        int col = nd * 8 + (lane & 3) * 2;
        float2 v0 = make_float2(O[nd][0] * inv0, O[nd][1] * inv0);
        float2 v1 = make_float2(O[nd][2] * inv1, O[nd][3] * inv1);
        *(float2*)&out[((size_t)b * SEQ + row_a) * HEAD + col]     = v0;
        *(float2*)&out[((size_t)b * SEQ + row_a + 8) * HEAD + col] = v1;
    }
}

// ---------------------------------------------------------------------------
extern "C" void kernel_launch(void* const* d_in, const int* in_sizes, int n_in,
                              void* d_out, int out_size)
{
    const float* x  = (const float*)d_in[0];
    const float* Wq = (const float*)d_in[1];
    const float* Wk = (const float*)d_in[2];
    const float* Wv = (const float*)d_in[3];
    float* out = (float*)d_out;

    cudaFuncSetAttribute(proj_kernel, cudaFuncAttributeMaxDynamicSharedMemorySize, PJ_SMEM);
    cudaFuncSetAttribute(attn_kernel, cudaFuncAttributeMaxDynamicSharedMemorySize, AT_SMEM);

    wprep_kernel<<<(192 * 1024 + 255) / 256, 256>>>(Wq, Wk, Wv);
    proj_kernel<<<128, 256, PJ_SMEM>>>(x);

    dim3 g2(32, BATCH);
    attn_kernel<<<g2, 128, AT_SMEM>>>(out);
}

// round 10
// speedup vs baseline: 6.3673x; 1.0313x over previous
#include <cuda_runtime.h>
#include <cuda_bf16.h>
#include <math.h>
#include <stdint.h>

#define BATCH 8
#define SEQ   2048
#define EMBED 1024
#define HEAD  64
#define MROWS (BATCH * SEQ)          // 16384

// Projected q,k,v as bf16 hi/lo pairs. q pre-scaled by log2(e)/32.
__device__ __nv_bfloat16 g_qh[MROWS * HEAD];
__device__ __nv_bfloat16 g_ql[MROWS * HEAD];
__device__ __nv_bfloat16 g_kh[MROWS * HEAD];
__device__ __nv_bfloat16 g_kl[MROWS * HEAD];
__device__ __nv_bfloat16 g_vh[MROWS * HEAD];
__device__ __nv_bfloat16 g_vl[MROWS * HEAD];

// W transposed: row = mat*64 + n (0..191), col = k (0..1023), bf16 hi/lo.
__device__ __nv_bfloat16 g_wth[192 * 1024];
__device__ __nv_bfloat16 g_wtl[192 * 1024];

#define QSCALE 0.045084220027780106f   // log2(e) / 32

// ---------------------------------------------------------------------------
// Helpers (mma.sync + ldmatrix + cp.async; compute_103-legal)
// ---------------------------------------------------------------------------
__device__ __forceinline__ uint32_t smem_u32(const void* p) {
    uint32_t a;
    asm("{ .reg .u64 t; cvta.to.shared.u64 t, %1; cvt.u32.u64 %0, t; }" : "=r"(a) : "l"(p));
    return a;
}
__device__ __forceinline__ void ldsm4(uint32_t* r, uint32_t a) {
    asm volatile("ldmatrix.sync.aligned.m8n8.x4.shared.b16 {%0,%1,%2,%3}, [%4];"
        : "=r"(r[0]), "=r"(r[1]), "=r"(r[2]), "=r"(r[3]) : "r"(a));
}
__device__ __forceinline__ void ldsm2(uint32_t* r, uint32_t a) {
    asm volatile("ldmatrix.sync.aligned.m8n8.x2.shared.b16 {%0,%1}, [%2];"
        : "=r"(r[0]), "=r"(r[1]) : "r"(a));
}
__device__ __forceinline__ void ldsm4t(uint32_t* r, uint32_t a) {
    asm volatile("ldmatrix.sync.aligned.m8n8.x4.trans.shared.b16 {%0,%1,%2,%3}, [%4];"
        : "=r"(r[0]), "=r"(r[1]), "=r"(r[2]), "=r"(r[3]) : "r"(a));
}
__device__ __forceinline__ void mma16816(float* c, const uint32_t* a, const uint32_t* b) {
    asm volatile("mma.sync.aligned.m16n8k16.row.col.f32.bf16.bf16.f32 "
        "{%0,%1,%2,%3}, {%4,%5,%6,%7}, {%8,%9}, {%0,%1,%2,%3};"
        : "+f"(c[0]), "+f"(c[1]), "+f"(c[2]), "+f"(c[3])
        : "r"(a[0]), "r"(a[1]), "r"(a[2]), "r"(a[3]), "r"(b[0]), "r"(b[1]));
}
__device__ __forceinline__ uint32_t f2bf2(float lo, float hi) {
    uint32_t r;
    asm("cvt.rn.bf16x2.f32 %0, %1, %2;" : "=r"(r) : "f"(hi), "f"(lo));
    return r;
}
__device__ __forceinline__ void split2(float v, float& hf, float& lf) {
    __nv_bfloat16 h = __float2bfloat16_rn(v);
    hf = __bfloat162float(h);
    lf = v - hf;
}
__device__ __forceinline__ void splitpack(float v0, float v1, uint32_t& ph, uint32_t& pl) {
    float h0, l0, h1, l1;
    split2(v0, h0, l0); split2(v1, h1, l1);
    ph = f2bf2(h0, h1);
    pl = f2bf2(l0, l1);
}
__device__ __forceinline__ float ex2(float x) {
    float r; asm("ex2.approx.ftz.f32 %0, %1;" : "=f"(r) : "f"(x)); return r;
}
__device__ __forceinline__ float qmax(float v) {
    v = fmaxf(v, __shfl_xor_sync(0xffffffffu, v, 1));
    v = fmaxf(v, __shfl_xor_sync(0xffffffffu, v, 2));
    return v;
}
__device__ __forceinline__ float qsum(float v) {
    v += __shfl_xor_sync(0xffffffffu, v, 1);
    v += __shfl_xor_sync(0xffffffffu, v, 2);
    return v;
}
__device__ __forceinline__ void cp16(uint32_t dst, const void* src) {
    asm volatile("cp.async.cg.shared.global [%0], [%1], 16;" :: "r"(dst), "l"(src));
}
#define CP_COMMIT() asm volatile("cp.async.commit_group;" ::: "memory")
#define CP_WAIT(n)  asm volatile("cp.async.wait_group %0;" :: "n"(n) : "memory")

#define PADB 144   // padded row pitch (bytes): conflict-free ldmatrix

// ---------------------------------------------------------------------------
// Kernel 0: W prep (unchanged)
// ---------------------------------------------------------------------------
__global__ __launch_bounds__(256) void wprep_kernel(
    const float* __restrict__ Wq,
    const float* __restrict__ Wk,
    const float* __restrict__ Wv)
{
    int i = blockIdx.x * 256 + threadIdx.x;
    if (i >= 192 * 1024) return;
    int row = i >> 10;
    int k   = i & 1023;
    int mat = row >> 6;
    int n   = row & 63;
    const float* W = (mat == 0) ? Wq : ((mat == 1) ? Wk : Wv);
    float v = W[(size_t)k * HEAD + n];
    float hf, lf; split2(v, hf, lf);
    g_wth[i] = __float2bfloat16_rn(hf);
    g_wtl[i] = __float2bfloat16_rn(lf);
}

// ---------------------------------------------------------------------------
// Kernel 1: QKV projection (3-term; q stores hi/lo scaled by log2(e)/32)
// ---------------------------------------------------------------------------
#define PJ_XH  0
#define PJ_XL  18432
#define PJ_WH  36864
#define PJ_WL  64512
#define PJ_SMEM 92160

__global__ __launch_bounds__(256) void proj_kernel(const float* __restrict__ x)
{
    extern __shared__ char smem[];
    const uint32_t sb = smem_u32(smem);
    const int tid  = threadIdx.x;
    const int w    = tid >> 5;
    const int lane = tid & 31;
    const int r0   = (w >> 1) * 32;
    const int c0   = (w & 1) * 96;
    const int row0 = blockIdx.x * 128;

    float C[2][12][4];
#pragma unroll
    for (int mt = 0; mt < 2; mt++)
#pragma unroll
        for (int nt = 0; nt < 12; nt++)
#pragma unroll
            for (int e = 0; e < 4; e++) C[mt][nt][e] = 0.f;

    const int a_row = (lane & 7) + ((lane >> 3) & 1) * 8;
    const int a_c16 = ((lane >> 4) & 1) * 16;
    const int b_row = lane & 7;
    const int b_c16 = ((lane >> 3) & 1) * 16;

    for (int c = 0; c < 16; c++) {
        const int k0 = c * 64;
        for (int i = tid; i < 2048; i += 256) {
            int r = i >> 4, c4 = i & 15;
            float4 v = *(const float4*)&x[(size_t)(row0 + r) * EMBED + k0 + c4 * 4];
            float h0, l0, h1, l1, h2, l2, h3, l3;
            split2(v.x, h0, l0); split2(v.y, h1, l1);
            split2(v.z, h2, l2); split2(v.w, h3, l3);
            int off = r * PADB + c4 * 8;
            *(uint32_t*)(smem + PJ_XH + off)     = f2bf2(h0, h1);
            *(uint32_t*)(smem + PJ_XH + off + 4) = f2bf2(h2, h3);
            *(uint32_t*)(smem + PJ_XL + off)     = f2bf2(l0, l1);
            *(uint32_t*)(smem + PJ_XL + off + 4) = f2bf2(l2, l3);
        }
        for (int i = tid; i < 1536; i += 256) {
            int row = i >> 3, d8 = i & 7;
            size_t src = ((size_t)row * 1024 + k0) / 8 + d8;
            int off = row * PADB + d8 * 16;
            *(uint4*)(smem + PJ_WH + off) = ((const uint4*)g_wth)[src];
            *(uint4*)(smem + PJ_WL + off) = ((const uint4*)g_wtl)[src];
        }
        __syncthreads();

#pragma unroll
        for (int kt = 0; kt < 4; kt++) {
            uint32_t Ah[2][4], Al[2][4];
#pragma unroll
            for (int mt = 0; mt < 2; mt++) {
                uint32_t ao = (uint32_t)((r0 + mt * 16 + a_row) * PADB + kt * 32 + a_c16);
                ldsm4(Ah[mt], sb + PJ_XH + ao);
                ldsm4(Al[mt], sb + PJ_XL + ao);
            }
#pragma unroll
            for (int nt = 0; nt < 12; nt++) {
                uint32_t bo = (uint32_t)((c0 + nt * 8 + b_row) * PADB + kt * 32 + b_c16);
                uint32_t Bh[2], Bl[2];
                ldsm2(Bh, sb + PJ_WH + bo);
                ldsm2(Bl, sb + PJ_WL + bo);
#pragma unroll
                for (int mt = 0; mt < 2; mt++) {
                    mma16816(C[mt][nt], Ah[mt], Bh);
                    mma16816(C[mt][nt], Ah[mt], Bl);
                    mma16816(C[mt][nt], Al[mt], Bh);
                }
            }
        }
        __syncthreads();
    }

#pragma unroll
    for (int mt = 0; mt < 2; mt++) {
#pragma unroll
        for (int nt = 0; nt < 12; nt++) {
            int col = c0 + nt * 8 + (lane & 3) * 2;
            int mat = col >> 6;
            int cc  = col & 63;
            int row_a = row0 + r0 + mt * 16 + (lane >> 2);
#pragma unroll
            for (int h = 0; h < 2; h++) {
                int row = row_a + h * 8;
                float s = (mat == 0) ? QSCALE : 1.0f;
                __nv_bfloat16* gh = (mat == 0) ? g_qh : ((mat == 1) ? g_kh : g_vh);
                __nv_bfloat16* gl = (mat == 0) ? g_ql : ((mat == 1) ? g_kl : g_vl);
                uint32_t ph, pl;
                splitpack(C[mt][nt][2 * h] * s, C[mt][nt][2 * h + 1] * s, ph, pl);
                *(uint32_t*)&gh[(size_t)row * HEAD + cc] = ph;
                *(uint32_t*)&gl[(size_t)row * HEAD + cc] = pl;
            }
        }
    }
}

// ---------------------------------------------------------------------------
// Kernel 2: causal flash attention. 3-term splits (R7 math), paired ldsm4,
// base-2 softmax, Q fragments hoisted to registers.
// CTA = 128 threads (4 warps), 64 q rows. Grid (32, 8), heavy-first.
// cp.async double-buffered K/V.
// ---------------------------------------------------------------------------
#define AT_QH   0
#define AT_QL   9216
#define AT_BUF0 18432
#define AT_BUF1 55296
#define AT_KHO  0
#define AT_KLO  9216
#define AT_VHO  18432
#define AT_VLO  27648
#define AT_SMEM 92160

__global__ __launch_bounds__(128) void attn_kernel(float* __restrict__ out)
{
    extern __shared__ char smem[];
    const uint32_t sb = smem_u32(smem);
    const int tid  = threadIdx.x;
    const int w    = tid >> 5;
    const int lane = tid & 31;
    const int qb   = 31 - blockIdx.x;      // heavy first
    const int b    = blockIdx.y;
    const int qbase = qb * 64;
    const int ntiles = qb + 1;

    auto issue_tile = [&](int kt, int buf) {
        const int kbase = kt * 64;
        const size_t gb = ((size_t)b * SEQ + kbase) * HEAD;
        const uint32_t bufb = sb + (buf ? AT_BUF1 : AT_BUF0);
#pragma unroll
        for (int i = tid; i < 2048; i += 128) {
            int arr = i >> 9, rem = i & 511;
            int r = rem >> 3, d8 = rem & 7;
            const __nv_bfloat16* src =
                (arr == 0) ? g_kh : ((arr == 1) ? g_kl : ((arr == 2) ? g_vh : g_vl));
            int aoff = (arr == 0) ? AT_KHO : ((arr == 1) ? AT_KLO : ((arr == 2) ? AT_VHO : AT_VLO));
            cp16(bufb + aoff + r * PADB + d8 * 16, src + gb + (size_t)r * HEAD + d8 * 8);
        }
        CP_COMMIT();
    };

    issue_tile(0, 0);

    // Q tile (64 x 64, hi/lo) -> smem -> register fragments (hoisted)
    {
        const uint4* qh = (const uint4*)(g_qh + ((size_t)b * SEQ + qbase) * HEAD);
        const uint4* ql = (const uint4*)(g_ql + ((size_t)b * SEQ + qbase) * HEAD);
        for (int i = tid; i < 1024; i += 128) {
            int arr = i >> 9, rem = i & 511;
            int r = rem >> 3, d8 = rem & 7;
            int off = (arr ? AT_QL : AT_QH) + r * PADB + d8 * 16;
            *(uint4*)(smem + off) = (arr ? ql : qh)[rem];
        }
    }
    __syncthreads();

    const int a_row = (lane & 7) + ((lane >> 3) & 1) * 8;
    const int a_c16 = ((lane >> 4) & 1) * 16;
    uint32_t QAh[4][4], QAl[4][4];
#pragma unroll
    for (int k4 = 0; k4 < 4; k4++) {
        uint32_t ao = (uint32_t)((w * 16 + a_row) * PADB + k4 * 32 + a_c16);
        ldsm4(QAh[k4], sb + AT_QH + ao);
        ldsm4(QAl[k4], sb + AT_QL + ao);
    }

    float O[8][4];
    float m_[2], l_[2];
#pragma unroll
    for (int nd = 0; nd < 8; nd++)
#pragma unroll
        for (int e = 0; e < 4; e++) O[nd][e] = 0.f;
    m_[0] = m_[1] = -1e30f;
    l_[0] = l_[1] = 0.f;

    // x4-paired B addressing: lanes 0-15 -> tile nt, lanes 16-31 -> tile nt+4
    const int bp_row = (lane & 7) + ((lane >> 4) & 1) * 32;
    const int bp_c16 = ((lane >> 3) & 1) * 16;
    // x4-paired trans (V): lanes 0-15 -> nd, 16-31 -> nd+4
    const int vp_row = lane & 15;
    const int vp_c16 = ((lane >> 4) & 1) * 64;

    for (int kt = 0; kt < ntiles; kt++) {
        const int cur = kt & 1;
        if (kt + 1 < ntiles) { issue_tile(kt + 1, 1 - cur); CP_WAIT(1); }
        else                 { CP_WAIT(0); }
        __syncthreads();

        const uint32_t bufb = sb + (cur ? AT_BUF1 : AT_BUF0);
        const int kbase = kt * 64;

        // ---- S = Qh·Kh + Qh·Kl + Ql·Kh ----
        float S[8][4];
#pragma unroll
        for (int nt = 0; nt < 8; nt++)
#pragma unroll
            for (int e = 0; e < 4; e++) S[nt][e] = 0.f;

#pragma unroll
        for (int k4 = 0; k4 < 4; k4++) {
            uint32_t KH[8][2], KL[8][2];
#pragma unroll
            for (int nt = 0; nt < 4; nt++) {
                uint32_t bo = (uint32_t)((nt * 8 + bp_row) * PADB + k4 * 32 + bp_c16);
                uint32_t r4[4];
                ldsm4(r4, bufb + AT_KHO + bo);
                KH[nt][0] = r4[0]; KH[nt][1] = r4[1];
                KH[nt + 4][0] = r4[2]; KH[nt + 4][1] = r4[3];
                ldsm4(r4, bufb + AT_KLO + bo);
                KL[nt][0] = r4[0]; KL[nt][1] = r4[1];
                KL[nt + 4][0] = r4[2]; KL[nt + 4][1] = r4[3];
            }
#pragma unroll
            for (int nt = 0; nt < 8; nt++) {
                mma16816(S[nt], QAh[k4], KH[nt]);
                mma16816(S[nt], QAh[k4], KL[nt]);
                mma16816(S[nt], QAl[k4], KH[nt]);
            }
        }

        // ---- mask (diagonal tile only) + online softmax (base 2) ----
        if (kt == ntiles - 1) {
            int rbase = qbase + w * 16 + (lane >> 2);
#pragma unroll
            for (int nt = 0; nt < 8; nt++) {
                int cb = kbase + nt * 8 + (lane & 3) * 2;
#pragma unroll
                for (int e = 0; e < 4; e++) {
                    int row = rbase + (e >> 1) * 8;
                    int col = cb + (e & 1);
                    if (col > row) S[nt][e] = -1e30f;
                }
            }
        }
#pragma unroll
        for (int h = 0; h < 2; h++) {
            float rm = -1e30f;
#pragma unroll
            for (int nt = 0; nt < 8; nt++)
                rm = fmaxf(rm, fmaxf(S[nt][2 * h], S[nt][2 * h + 1]));
            rm = qmax(rm);
            float mn = fmaxf(m_[h], rm);
            float sc = ex2(m_[h] - mn);
            m_[h] = mn;
            float rs = 0.f;
#pragma unroll
            for (int nt = 0; nt < 8; nt++) {
                float p0 = ex2(S[nt][2 * h] - mn);
                float p1 = ex2(S[nt][2 * h + 1] - mn);
                S[nt][2 * h] = p0; S[nt][2 * h + 1] = p1;
                rs += p0 + p1;
            }
            rs = qsum(rs);
            l_[h] = l_[h] * sc + rs;
#pragma unroll
            for (int nd = 0; nd < 8; nd++) {
                O[nd][2 * h]     *= sc;
                O[nd][2 * h + 1] *= sc;
            }
        }

        // ---- O += Ph·Vh + Ph·Vl + Pl·Vh ----
#pragma unroll
        for (int k4 = 0; k4 < 4; k4++) {
            uint32_t Ph[4], Pl[4];
            splitpack(S[2 * k4][0],     S[2 * k4][1],     Ph[0], Pl[0]);
            splitpack(S[2 * k4][2],     S[2 * k4][3],     Ph[1], Pl[1]);
            splitpack(S[2 * k4 + 1][0], S[2 * k4 + 1][1], Ph[2], Pl[2]);
            splitpack(S[2 * k4 + 1][2], S[2 * k4 + 1][3], Ph[3], Pl[3]);
            uint32_t VH[8][2], VL[8][2];
#pragma unroll
            for (int nd = 0; nd < 4; nd++) {
                uint32_t vo = (uint32_t)((k4 * 16 + vp_row) * PADB + nd * 16 + vp_c16);
                uint32_t r4[4];
                ldsm4t(r4, bufb + AT_VHO + vo);
                VH[nd][0] = r4[0]; VH[nd][1] = r4[1];
                VH[nd + 4][0] = r4[2]; VH[nd + 4][1] = r4[3];
                ldsm4t(r4, bufb + AT_VLO + vo);
                VL[nd][0] = r4[0]; VL[nd][1] = r4[1];
                VL[nd + 4][0] = r4[2]; VL[nd + 4][1] = r4[3];
            }
#pragma unroll
            for (int nd = 0; nd < 8; nd++) {
                mma16816(O[nd], Ph, VH[nd]);
                mma16816(O[nd], Ph, VL[nd]);
                mma16816(O[nd], Pl, VH[nd]);
            }
        }
        __syncthreads();
    }

    // ---- store ----
    float inv0 = 1.f / l_[0];
    float inv1 = 1.f / l_[1];
    int row_a = qbase + w * 16 + (lane >> 2);
#pragma unroll
    for (int nd = 0; nd < 8; nd++) {
        int col = nd * 8 + (lane & 3) * 2;
        float2 v0 = make_float2(O[nd][0] * inv0, O[nd][1] * inv0);
        float2 v1 = make_float2(O[nd][2] * inv1, O[nd][3] * inv1);
        *(float2*)&out[((size_t)b * SEQ + row_a) * HEAD + col]     = v0;
        *(float2*)&out[((size_t)b * SEQ + row_a + 8) * HEAD + col] = v1;
    }
}

// ---------------------------------------------------------------------------
extern "C" void kernel_launch(void* const* d_in, const int* in_sizes, int n_in,
                              void* d_out, int out_size)
{
    const float* x  = (const float*)d_in[0];
    const float* Wq = (const float*)d_in[1];
    const float* Wk = (const float*)d_in[2];
    const float* Wv = (const float*)d_in[3];
    float* out = (float*)d_out;

    cudaFuncSetAttribute(proj_kernel, cudaFuncAttributeMaxDynamicSharedMemorySize, PJ_SMEM);
    cudaFuncSetAttribute(attn_kernel, cudaFuncAttributeMaxDynamicSharedMemorySize, AT_SMEM);

    wprep_kernel<<<(192 * 1024 + 255) / 256, 256>>>(Wq, Wk, Wv);
    proj_kernel<<<128, 256, PJ_SMEM>>>(x);

    dim3 g2(32, BATCH);
    attn_kernel<<<g2, 128, AT_SMEM>>>(out);
}